// round 1
// baseline (speedup 1.0000x reference)
#include <cuda_runtime.h>
#include <cuda_bf16.h>
#include <math.h>

// Problem dims (fixed by the dataset)
#define BB 2
#define SS 2048
#define HH 1024
#define NHEAD 16
#define HD 64
#define MM (BB*SS)          // 4096 rows

// ---------------------------------------------------------------------------
// Scratch (device globals: allocation-free rule)
// ---------------------------------------------------------------------------
__device__ float g_Q[MM * HH];
__device__ float g_K[MM * HH];
__device__ float g_V[MM * HH];
__device__ float g_C[MM * HH];
__device__ float g_cos[SS * 32];
__device__ float g_sin[SS * 32];

// ---------------------------------------------------------------------------
// GEMM: C[M,N] = A[M,K] @ W[K,N] + bias[N]   (all row-major, fp32)
// 128x128 block, BK=8, 256 threads, 8x8 microtile
// ---------------------------------------------------------------------------
__global__ void __launch_bounds__(256) gemm_bias(
    const float* __restrict__ A, const float* __restrict__ W,
    const float* __restrict__ bias, float* __restrict__ C,
    int M, int N, int K)
{
    __shared__ float As[8][132];   // transposed A tile, padded vs bank conflicts
    __shared__ float Bs[8][128];

    const int tid = threadIdx.x;
    const int tx  = tid & 15;
    const int ty  = tid >> 4;
    const int rowBase = blockIdx.y * 128;
    const int colBase = blockIdx.x * 128;

    const int aRow = tid >> 1;          // 0..127
    const int aCol = (tid & 1) << 2;    // 0 or 4
    const int bRow = tid >> 5;          // 0..7
    const int bCol = (tid & 31) << 2;   // 0..124

    const float* Ap = A + (size_t)(rowBase + aRow) * K + aCol;
    const float* Wp = W + (size_t)bRow * N + colBase + bCol;

    float acc[8][8];
    #pragma unroll
    for (int i = 0; i < 8; i++)
        #pragma unroll
        for (int j = 0; j < 8; j++) acc[i][j] = 0.0f;

    for (int k0 = 0; k0 < K; k0 += 8) {
        float4 a4 = *reinterpret_cast<const float4*>(Ap + k0);
        float4 b4 = *reinterpret_cast<const float4*>(Wp + (size_t)k0 * N);
        As[aCol + 0][aRow] = a4.x;
        As[aCol + 1][aRow] = a4.y;
        As[aCol + 2][aRow] = a4.z;
        As[aCol + 3][aRow] = a4.w;
        *reinterpret_cast<float4*>(&Bs[bRow][bCol]) = b4;
        __syncthreads();

        #pragma unroll
        for (int kk = 0; kk < 8; kk++) {
            float af[8], bf[8];
            *reinterpret_cast<float4*>(&af[0]) = *reinterpret_cast<const float4*>(&As[kk][ty * 8]);
            *reinterpret_cast<float4*>(&af[4]) = *reinterpret_cast<const float4*>(&As[kk][ty * 8 + 4]);
            *reinterpret_cast<float4*>(&bf[0]) = *reinterpret_cast<const float4*>(&Bs[kk][tx * 8]);
            *reinterpret_cast<float4*>(&bf[4]) = *reinterpret_cast<const float4*>(&Bs[kk][tx * 8 + 4]);
            #pragma unroll
            for (int i = 0; i < 8; i++)
                #pragma unroll
                for (int j = 0; j < 8; j++)
                    acc[i][j] = fmaf(af[i], bf[j], acc[i][j]);
        }
        __syncthreads();
    }

    #pragma unroll
    for (int i = 0; i < 8; i++) {
        const size_t r = (size_t)(rowBase + ty * 8 + i);
        #pragma unroll
        for (int j = 0; j < 8; j += 4) {
            float4 o;
            o.x = acc[i][j + 0] + bias[colBase + tx * 8 + j + 0];
            o.y = acc[i][j + 1] + bias[colBase + tx * 8 + j + 1];
            o.z = acc[i][j + 2] + bias[colBase + tx * 8 + j + 2];
            o.w = acc[i][j + 3] + bias[colBase + tx * 8 + j + 3];
            *reinterpret_cast<float4*>(&C[r * N + colBase + tx * 8 + j]) = o;
        }
    }
}

// ---------------------------------------------------------------------------
// RoPE table: theta computed in fp32 (matching reference rounding), cos/sin in
// double (safe even if the build uses fast-math).
// ---------------------------------------------------------------------------
__global__ void rope_table_kernel()
{
    int i = blockIdx.x * blockDim.x + threadIdx.x;
    if (i >= SS * 32) return;
    int s = i >> 5;
    int d = i & 31;
    float inv = 1.0f / powf(10000.0f, (float)d / 32.0f);
    float th  = (float)s * inv;           // fp32 product, like the reference
    g_cos[i] = (float)cos((double)th);
    g_sin[i] = (float)sin((double)th);
}

// Apply RoPE in place to Q and K. One thread per (row, head, d<32) pair.
__global__ void rope_apply_kernel(float* __restrict__ Q, float* __restrict__ K)
{
    int idx = blockIdx.x * blockDim.x + threadIdx.x;
    const int total = MM * NHEAD * 32;
    if (idx >= total) return;
    int d   = idx & 31;
    int h   = (idx >> 5) & 15;
    int r   = idx >> 9;           // row in [0, 4096)
    int s   = r & (SS - 1);
    float c  = g_cos[s * 32 + d];
    float sn = g_sin[s * 32 + d];
    size_t base = (size_t)r * HH + h * HD + d;

    float q0 = Q[base], q1 = Q[base + 32];
    Q[base]      = q0 * c - q1 * sn;
    Q[base + 32] = q1 * c + q0 * sn;

    float k0 = K[base], k1 = K[base + 32];
    K[base]      = k0 * c - k1 * sn;
    K[base + 32] = k1 * c + k0 * sn;
}

// ---------------------------------------------------------------------------
// Flash attention: block = (64 queries) x (head, batch). 256 threads,
// 16x16 thread grid, 4x4 microtiles. Online softmax, P staged via smem.
// smem: Qs 64x64, Ks 64x65, Vs 64x65, Ps 64x64, Ms 64  -> 66304 bytes
// ---------------------------------------------------------------------------
#define ATTN_SMEM ((64*64 + 64*65 + 64*65 + 64*64 + 64) * 4)

__global__ void __launch_bounds__(256) attn_kernel(
    const float* __restrict__ Q, const float* __restrict__ K,
    const float* __restrict__ V, const float* __restrict__ mask,
    float* __restrict__ Ctx)
{
    extern __shared__ float sm[];
    float* Qs = sm;                  // [64][64]
    float* Ks = Qs + 64 * 64;        // [64][65]
    float* Vs = Ks + 64 * 65;        // [64][65]
    float* Ps = Vs + 64 * 65;        // [64][64]
    float* Ms = Ps + 64 * 64;        // [64]

    const int b  = blockIdx.z;
    const int h  = blockIdx.y;
    const int q0 = blockIdx.x * 64;
    const int tid = threadIdx.x;
    const int tx  = tid & 15;
    const int ty  = tid >> 4;

    const float* Qb = Q + (size_t)(b * SS) * HH + h * HD;
    const float* Kb = K + (size_t)(b * SS) * HH + h * HD;
    const float* Vb = V + (size_t)(b * SS) * HH + h * HD;
    const float* mb = mask + b * SS;

    // load Q tile (64 rows x 64 dims) as float4
    for (int i = tid; i < 64 * 16; i += 256) {
        int r  = i >> 4;
        int c4 = (i & 15) << 2;
        float4 v4 = *reinterpret_cast<const float4*>(Qb + (size_t)(q0 + r) * HH + c4);
        *reinterpret_cast<float4*>(&Qs[r * 64 + c4]) = v4;
    }

    float Oacc[4][4];
    float m_run[4], l_run[4];
    #pragma unroll
    for (int i = 0; i < 4; i++) {
        m_run[i] = -1e30f;
        l_run[i] = 0.0f;
        #pragma unroll
        for (int j = 0; j < 4; j++) Oacc[i][j] = 0.0f;
    }

    const int nkt = (q0 >> 6) + 1;   // causal: key tiles 0..q-tile

    for (int kt = 0; kt < nkt; kt++) {
        const int k0 = kt * 64;
        // load K, V tiles (scalar stores into padded smem)
        for (int i = tid; i < 64 * 16; i += 256) {
            int r  = i >> 4;
            int c4 = (i & 15) << 2;
            float4 kv = *reinterpret_cast<const float4*>(Kb + (size_t)(k0 + r) * HH + c4);
            Ks[r * 65 + c4 + 0] = kv.x; Ks[r * 65 + c4 + 1] = kv.y;
            Ks[r * 65 + c4 + 2] = kv.z; Ks[r * 65 + c4 + 3] = kv.w;
            float4 vv = *reinterpret_cast<const float4*>(Vb + (size_t)(k0 + r) * HH + c4);
            Vs[r * 65 + c4 + 0] = vv.x; Vs[r * 65 + c4 + 1] = vv.y;
            Vs[r * 65 + c4 + 2] = vv.z; Vs[r * 65 + c4 + 3] = vv.w;
        }
        if (tid < 64) Ms[tid] = mb[k0 + tid];
        __syncthreads();

        // S = Q @ K^T   (4x4 per thread)
        float sacc[4][4];
        #pragma unroll
        for (int i = 0; i < 4; i++)
            #pragma unroll
            for (int j = 0; j < 4; j++) sacc[i][j] = 0.0f;

        #pragma unroll 4
        for (int d = 0; d < 64; d++) {
            float qf[4], kf[4];
            #pragma unroll
            for (int i = 0; i < 4; i++) qf[i] = Qs[(ty * 4 + i) * 64 + d];
            #pragma unroll
            for (int j = 0; j < 4; j++) kf[j] = Ks[(tx * 4 + j) * 65 + d];
            #pragma unroll
            for (int i = 0; i < 4; i++)
                #pragma unroll
                for (int j = 0; j < 4; j++)
                    sacc[i][j] = fmaf(qf[i], kf[j], sacc[i][j]);
        }

        // scale + pad mask + causal (diagonal tile only)
        const bool diag = (kt == nkt - 1);
        #pragma unroll
        for (int i = 0; i < 4; i++) {
            #pragma unroll
            for (int j = 0; j < 4; j++) {
                float sv = sacc[i][j] * 0.125f;               // 1/sqrt(64)
                sv += (1.0f - Ms[tx * 4 + j]) * (-1e4f);      // pad
                if (diag) {
                    int qg = q0 + ty * 4 + i;
                    int kg = k0 + tx * 4 + j;
                    if (kg > qg) sv += -1e10f;                // causal (added, as in ref)
                }
                sacc[i][j] = sv;
            }
        }

        // online softmax (rows live across 16 consecutive lanes)
        #pragma unroll
        for (int i = 0; i < 4; i++) {
            float mm = fmaxf(fmaxf(sacc[i][0], sacc[i][1]), fmaxf(sacc[i][2], sacc[i][3]));
            #pragma unroll
            for (int off = 8; off >= 1; off >>= 1)
                mm = fmaxf(mm, __shfl_xor_sync(0xffffffffu, mm, off));
            float mnew  = fmaxf(m_run[i], mm);
            float alpha = __expf(m_run[i] - mnew);
            float ls = 0.0f;
            #pragma unroll
            for (int j = 0; j < 4; j++) {
                float p = __expf(sacc[i][j] - mnew);
                Ps[(ty * 4 + i) * 64 + tx * 4 + j] = p;
                ls += p;
            }
            #pragma unroll
            for (int off = 8; off >= 1; off >>= 1)
                ls += __shfl_xor_sync(0xffffffffu, ls, off);
            l_run[i] = l_run[i] * alpha + ls;
            m_run[i] = mnew;
            #pragma unroll
            for (int j = 0; j < 4; j++) Oacc[i][j] *= alpha;
        }
        __syncthreads();

        // O += P @ V
        #pragma unroll 4
        for (int kk = 0; kk < 64; kk++) {
            float pf[4], vf[4];
            #pragma unroll
            for (int i = 0; i < 4; i++) pf[i] = Ps[(ty * 4 + i) * 64 + kk];
            #pragma unroll
            for (int j = 0; j < 4; j++) vf[j] = Vs[kk * 65 + tx * 4 + j];
            #pragma unroll
            for (int i = 0; i < 4; i++)
                #pragma unroll
                for (int j = 0; j < 4; j++)
                    Oacc[i][j] = fmaf(pf[i], vf[j], Oacc[i][j]);
        }
        __syncthreads();
    }

    // write ctx (layout [B,S,NH,HD] == [M,H])
    float* Cb = Ctx + (size_t)(b * SS) * HH + h * HD;
    #pragma unroll
    for (int i = 0; i < 4; i++) {
        float inv_l = 1.0f / l_run[i];
        #pragma unroll
        for (int j = 0; j < 4; j++)
            Cb[(size_t)(q0 + ty * 4 + i) * HH + tx * 4 + j] = Oacc[i][j] * inv_l;
    }
}

// ---------------------------------------------------------------------------
// launcher
// ---------------------------------------------------------------------------
extern "C" void kernel_launch(void* const* d_in, const int* in_sizes, int n_in,
                              void* d_out, int out_size)
{
    const float* X    = (const float*)d_in[0];
    const float* mask = (const float*)d_in[1];
    const float* Wq   = (const float*)d_in[2];
    const float* bq   = (const float*)d_in[3];
    const float* Wk   = (const float*)d_in[4];
    const float* bk   = (const float*)d_in[5];
    const float* Wv   = (const float*)d_in[6];
    const float* bv   = (const float*)d_in[7];
    const float* Wo   = (const float*)d_in[8];
    const float* bo   = (const float*)d_in[9];
    float* out = (float*)d_out;

    float *qp, *kp, *vp, *cp;
    cudaGetSymbolAddress((void**)&qp, g_Q);
    cudaGetSymbolAddress((void**)&kp, g_K);
    cudaGetSymbolAddress((void**)&vp, g_V);
    cudaGetSymbolAddress((void**)&cp, g_C);

    const int M = MM, N = HH, K = HH;
    dim3 gg(N / 128, M / 128);

    gemm_bias<<<gg, 256>>>(X, Wq, bq, qp, M, N, K);
    gemm_bias<<<gg, 256>>>(X, Wk, bk, kp, M, N, K);
    gemm_bias<<<gg, 256>>>(X, Wv, bv, vp, M, N, K);

    rope_table_kernel<<<(SS * 32 + 255) / 256, 256>>>();
    {
        const int total = MM * NHEAD * 32;
        rope_apply_kernel<<<(total + 255) / 256, 256>>>(qp, kp);
    }

    cudaFuncSetAttribute(attn_kernel, cudaFuncAttributeMaxDynamicSharedMemorySize, ATTN_SMEM);
    attn_kernel<<<dim3(SS / 64, NHEAD, BB), 256, ATTN_SMEM>>>(qp, kp, vp, mask, cp);

    gemm_bias<<<gg, 256>>>(cp, Wo, bo, out, M, N, K);
}

// round 4
// speedup vs baseline: 1.4305x; 1.4305x over previous
#include <cuda_runtime.h>
#include <cuda_bf16.h>
#include <math.h>
#include <stdint.h>

// Problem dims (fixed by the dataset)
#define BB 2
#define SS 2048
#define HH 1024
#define NHEAD 16
#define HD 64
#define MM (BB*SS)          // 4096 rows

// ---------------------------------------------------------------------------
// Scratch (device globals: allocation-free rule)
// ---------------------------------------------------------------------------
__device__ float g_Q[MM * HH];
__device__ float g_K[MM * HH];
__device__ float g_V[MM * HH];
__device__ float g_C[MM * HH];
__device__ float g_cos[SS * 32];
__device__ float g_sin[SS * 32];
__device__ __nv_bfloat16 g_Xhi[MM * HH];
__device__ __nv_bfloat16 g_Xlo[MM * HH];
__device__ __nv_bfloat16 g_Chi[MM * HH];
__device__ __nv_bfloat16 g_Clo[MM * HH];
__device__ __nv_bfloat16 g_Whi[4 * HH * HH];   // W^T hi, [N,K] per weight
__device__ __nv_bfloat16 g_Wlo[4 * HH * HH];   // W^T lo

// ---------------------------------------------------------------------------
// PTX helpers (sm_80-baseline features only: ldmatrix / mma.sync / cp.async)
// ---------------------------------------------------------------------------
__device__ __forceinline__ uint32_t smem_u32(const void* p) {
    uint32_t a;
    asm("{ .reg .u64 t; cvta.to.shared.u64 t, %1; cvt.u32.u64 %0, t; }" : "=r"(a) : "l"(p));
    return a;
}
#define CP_ASYNC16(s, g) \
    asm volatile("cp.async.cg.shared.global [%0], [%1], 16;" :: "r"(s), "l"(g))
#define CP_COMMIT() asm volatile("cp.async.commit_group;" ::: "memory")
#define CP_WAIT1()  asm volatile("cp.async.wait_group 1;" ::: "memory")

__device__ __forceinline__ void ldsm_x4(uint32_t* r, uint32_t addr) {
    asm volatile("ldmatrix.sync.aligned.m8n8.x4.shared.b16 {%0,%1,%2,%3}, [%4];"
                 : "=r"(r[0]), "=r"(r[1]), "=r"(r[2]), "=r"(r[3]) : "r"(addr));
}
// B tile is [N,K] row-major (= col-major KxN): NON-trans x2 gives the b
// fragment directly (fragment row = n = lane/4, reg pair consecutive in k).
__device__ __forceinline__ void ldsm_x2(uint32_t* r, uint32_t addr) {
    asm volatile("ldmatrix.sync.aligned.m8n8.x2.shared.b16 {%0,%1}, [%2];"
                 : "=r"(r[0]), "=r"(r[1]) : "r"(addr));
}
__device__ __forceinline__ void mma_bf16(float* c, const uint32_t* a, const uint32_t* b) {
    asm volatile("mma.sync.aligned.m16n8k16.row.col.f32.bf16.bf16.f32 "
                 "{%0,%1,%2,%3}, {%4,%5,%6,%7}, {%8,%9}, {%0,%1,%2,%3};"
                 : "+f"(c[0]), "+f"(c[1]), "+f"(c[2]), "+f"(c[3])
                 : "r"(a[0]), "r"(a[1]), "r"(a[2]), "r"(a[3]), "r"(b[0]), "r"(b[1]));
}

// ---------------------------------------------------------------------------
// Prep: fp32 -> (hi, lo) bf16 split
// ---------------------------------------------------------------------------
__global__ void split_kernel(const float* __restrict__ x,
                             __nv_bfloat16* __restrict__ hi,
                             __nv_bfloat16* __restrict__ lo, int n4)
{
    int i = blockIdx.x * blockDim.x + threadIdx.x;
    if (i >= n4) return;
    float4 v = reinterpret_cast<const float4*>(x)[i];
    __nv_bfloat16 h[4], l[4];
    float f[4] = {v.x, v.y, v.z, v.w};
    #pragma unroll
    for (int j = 0; j < 4; j++) {
        h[j] = __float2bfloat16(f[j]);
        l[j] = __float2bfloat16(f[j] - __bfloat162float(h[j]));
    }
    reinterpret_cast<ushort4*>(hi)[i] = make_ushort4(
        __bfloat16_as_ushort(h[0]), __bfloat16_as_ushort(h[1]),
        __bfloat16_as_ushort(h[2]), __bfloat16_as_ushort(h[3]));
    reinterpret_cast<ushort4*>(lo)[i] = make_ushort4(
        __bfloat16_as_ushort(l[0]), __bfloat16_as_ushort(l[1]),
        __bfloat16_as_ushort(l[2]), __bfloat16_as_ushort(l[3]));
}

// Transpose + split 4 weights: W[k,n] -> WT[n,k] hi/lo
__global__ void wsplit_kernel(const float* __restrict__ W0, const float* __restrict__ W1,
                              const float* __restrict__ W2, const float* __restrict__ W3)
{
    __shared__ float t[32][33];
    int w = blockIdx.z;
    const float* W = (w == 0) ? W0 : (w == 1) ? W1 : (w == 2) ? W2 : W3;
    int bn = blockIdx.x * 32;   // n block
    int bk = blockIdx.y * 32;   // k block
    int x = threadIdx.x, y = threadIdx.y;   // 32 x 8
    #pragma unroll
    for (int j = 0; j < 32; j += 8)
        t[y + j][x] = W[(size_t)(bk + y + j) * HH + bn + x];
    __syncthreads();
    size_t base = (size_t)w * HH * HH;
    #pragma unroll
    for (int j = 0; j < 32; j += 8) {
        float v = t[x][y + j];
        __nv_bfloat16 h = __float2bfloat16(v);
        __nv_bfloat16 l = __float2bfloat16(v - __bfloat162float(h));
        size_t o = base + (size_t)(bn + y + j) * HH + bk + x;
        g_Whi[o] = h;
        g_Wlo[o] = l;
    }
}

// ---------------------------------------------------------------------------
// Tensor-core GEMM (bf16x3 via mma.sync):
//   C[M,N] = A @ W + bias,  A hi/lo [M,K] row-major, B = W^T hi/lo [N,K] row-major
// CTA tile 128x128, K-chunk 32, 8 warps (each 64x32), cp.async double buffer.
// smem stage: 4 tiles of [128][40] bf16 (pad 8) = 40960 B; 2 stages = 81920 B
// ---------------------------------------------------------------------------
#define TILE_E   (128 * 40)                 // elems per tile
#define STAGE_E  (4 * TILE_E)               // elems per stage
#define GT_SMEM  (2 * STAGE_E * 2)          // bytes

__global__ void __launch_bounds__(256) tc_gemm(
    const __nv_bfloat16* __restrict__ Ahi, const __nv_bfloat16* __restrict__ Alo,
    const __nv_bfloat16* __restrict__ Bhi, const __nv_bfloat16* __restrict__ Blo,
    const float* __restrict__ bias, float* __restrict__ C)
{
    extern __shared__ __nv_bfloat16 sm[];
    const int tid  = threadIdx.x;
    const int lane = tid & 31;
    const int w    = tid >> 5;
    const int wm   = (w & 1) * 64;   // warp row offset within CTA tile
    const int wn   = (w >> 1) * 32;  // warp col offset within CTA tile
    const int rowBase = blockIdx.y * 128;
    const int colBase = blockIdx.x * 128;

    const uint32_t sb = smem_u32(sm);

    // global row bases per tile id {Ahi, Alo, Bhi, Blo}
    const __nv_bfloat16* gsel[4] = {
        Ahi + (size_t)rowBase * HH, Alo + (size_t)rowBase * HH,
        Bhi + (size_t)colBase * HH, Blo + (size_t)colBase * HH };

    // issue one stage of cp.async copies
    auto issue = [&](int st, int k0) {
        uint32_t sbase = sb + (uint32_t)(st * STAGE_E * 2);
        #pragma unroll
        for (int t = 0; t < 8; t++) {
            int i    = t * 256 + tid;        // 0..2047
            int tile = i >> 9;               // 0..3
            int r    = (i >> 2) & 127;
            int c    = i & 3;                // 16B chunk (8 bf16)
            uint32_t sa = sbase + (uint32_t)((tile * TILE_E + r * 40 + c * 8) * 2);
            const __nv_bfloat16* ga = gsel[tile] + (size_t)r * HH + k0 + c * 8;
            CP_ASYNC16(sa, ga);
        }
    };

    float acc[4][4][4];
    #pragma unroll
    for (int mt = 0; mt < 4; mt++)
        #pragma unroll
        for (int nt = 0; nt < 4; nt++)
            #pragma unroll
            for (int q = 0; q < 4; q++) acc[mt][nt][q] = 0.0f;

    issue(0, 0);
    CP_COMMIT();

    const int nIter = HH / 32;   // 32
    for (int it = 0; it < nIter; it++) {
        if (it + 1 < nIter) issue((it + 1) & 1, (it + 1) * 32);
        CP_COMMIT();
        CP_WAIT1();
        __syncthreads();

        uint32_t stage = sb + (uint32_t)((it & 1) * STAGE_E * 2);
        #pragma unroll
        for (int ks = 0; ks < 32; ks += 16) {
            #pragma unroll
            for (int combo = 0; combo < 3; combo++) {
                const int selA = (combo == 2) ? 1 : 0;       // lo A only in combo 2
                const int selB = (combo == 1) ? 1 : 0;       // lo B only in combo 1
                uint32_t abase = stage + (uint32_t)(selA * TILE_E * 2);
                uint32_t bbase = stage + (uint32_t)((2 + selB) * TILE_E * 2);

                uint32_t a[4][4];
                #pragma unroll
                for (int mt = 0; mt < 4; mt++) {
                    uint32_t addr = abase + (uint32_t)(((wm + mt * 16 + (lane & 15)) * 40
                                     + ks + ((lane >> 4) << 3)) * 2);
                    ldsm_x4(a[mt], addr);
                }
                #pragma unroll
                for (int nt = 0; nt < 4; nt++) {
                    uint32_t b[2];
                    uint32_t addr = bbase + (uint32_t)(((wn + nt * 8 + (lane & 7)) * 40
                                     + ks + (((lane >> 3) & 1) << 3)) * 2);
                    ldsm_x2(b, addr);
                    #pragma unroll
                    for (int mt = 0; mt < 4; mt++)
                        mma_bf16(acc[mt][nt], a[mt], b);
                }
            }
        }
        __syncthreads();
    }

    // epilogue: add bias, write fp32 C
    #pragma unroll
    for (int mt = 0; mt < 4; mt++) {
        int r0 = rowBase + wm + mt * 16 + (lane >> 2);
        #pragma unroll
        for (int nt = 0; nt < 4; nt++) {
            int cc = colBase + wn + nt * 8 + (lane & 3) * 2;
            float b0 = bias[cc], b1 = bias[cc + 1];
            float2 v0 = make_float2(acc[mt][nt][0] + b0, acc[mt][nt][1] + b1);
            float2 v1 = make_float2(acc[mt][nt][2] + b0, acc[mt][nt][3] + b1);
            *reinterpret_cast<float2*>(&C[(size_t)r0 * HH + cc]) = v0;
            *reinterpret_cast<float2*>(&C[(size_t)(r0 + 8) * HH + cc]) = v1;
        }
    }
}

// ---------------------------------------------------------------------------
// RoPE table + apply (unchanged, verified in R1)
// ---------------------------------------------------------------------------
__global__ void rope_table_kernel()
{
    int i = blockIdx.x * blockDim.x + threadIdx.x;
    if (i >= SS * 32) return;
    int s = i >> 5;
    int d = i & 31;
    float inv = 1.0f / powf(10000.0f, (float)d / 32.0f);
    float th  = (float)s * inv;
    g_cos[i] = (float)cos((double)th);
    g_sin[i] = (float)sin((double)th);
}

__global__ void rope_apply_kernel(float* __restrict__ Q, float* __restrict__ K)
{
    int idx = blockIdx.x * blockDim.x + threadIdx.x;
    const int total = MM * NHEAD * 32;
    if (idx >= total) return;
    int d   = idx & 31;
    int h   = (idx >> 5) & 15;
    int r   = idx >> 9;
    int s   = r & (SS - 1);
    float c  = g_cos[s * 32 + d];
    float sn = g_sin[s * 32 + d];
    size_t base = (size_t)r * HH + h * HD + d;

    float q0 = Q[base], q1 = Q[base + 32];
    Q[base]      = q0 * c - q1 * sn;
    Q[base + 32] = q1 * c + q0 * sn;

    float k0 = K[base], k1 = K[base + 32];
    K[base]      = k0 * c - k1 * sn;
    K[base + 32] = k1 * c + k0 * sn;
}

// ---------------------------------------------------------------------------
// Flash attention (unchanged, verified in R1)
// ---------------------------------------------------------------------------
#define ATTN_SMEM ((64*64 + 64*65 + 64*65 + 64*64 + 64) * 4)

__global__ void __launch_bounds__(256) attn_kernel(
    const float* __restrict__ Q, const float* __restrict__ K,
    const float* __restrict__ V, const float* __restrict__ mask,
    float* __restrict__ Ctx)
{
    extern __shared__ float smf[];
    float* Qs = smf;
    float* Ks = Qs + 64 * 64;
    float* Vs = Ks + 64 * 65;
    float* Ps = Vs + 64 * 65;
    float* Ms = Ps + 64 * 64;

    const int b  = blockIdx.z;
    const int h  = blockIdx.y;
    const int q0 = blockIdx.x * 64;
    const int tid = threadIdx.x;
    const int tx  = tid & 15;
    const int ty  = tid >> 4;

    const float* Qb = Q + (size_t)(b * SS) * HH + h * HD;
    const float* Kb = K + (size_t)(b * SS) * HH + h * HD;
    const float* Vb = V + (size_t)(b * SS) * HH + h * HD;
    const float* mb = mask + b * SS;

    for (int i = tid; i < 64 * 16; i += 256) {
        int r  = i >> 4;
        int c4 = (i & 15) << 2;
        float4 v4 = *reinterpret_cast<const float4*>(Qb + (size_t)(q0 + r) * HH + c4);
        *reinterpret_cast<float4*>(&Qs[r * 64 + c4]) = v4;
    }

    float Oacc[4][4];
    float m_run[4], l_run[4];
    #pragma unroll
    for (int i = 0; i < 4; i++) {
        m_run[i] = -1e30f;
        l_run[i] = 0.0f;
        #pragma unroll
        for (int j = 0; j < 4; j++) Oacc[i][j] = 0.0f;
    }

    const int nkt = (q0 >> 6) + 1;

    for (int kt = 0; kt < nkt; kt++) {
        const int k0 = kt * 64;
        for (int i = tid; i < 64 * 16; i += 256) {
            int r  = i >> 4;
            int c4 = (i & 15) << 2;
            float4 kv = *reinterpret_cast<const float4*>(Kb + (size_t)(k0 + r) * HH + c4);
            Ks[r * 65 + c4 + 0] = kv.x; Ks[r * 65 + c4 + 1] = kv.y;
            Ks[r * 65 + c4 + 2] = kv.z; Ks[r * 65 + c4 + 3] = kv.w;
            float4 vv = *reinterpret_cast<const float4*>(Vb + (size_t)(k0 + r) * HH + c4);
            Vs[r * 65 + c4 + 0] = vv.x; Vs[r * 65 + c4 + 1] = vv.y;
            Vs[r * 65 + c4 + 2] = vv.z; Vs[r * 65 + c4 + 3] = vv.w;
        }
        if (tid < 64) Ms[tid] = mb[k0 + tid];
        __syncthreads();

        float sacc[4][4];
        #pragma unroll
        for (int i = 0; i < 4; i++)
            #pragma unroll
            for (int j = 0; j < 4; j++) sacc[i][j] = 0.0f;

        #pragma unroll 4
        for (int d = 0; d < 64; d++) {
            float qf[4], kf[4];
            #pragma unroll
            for (int i = 0; i < 4; i++) qf[i] = Qs[(ty * 4 + i) * 64 + d];
            #pragma unroll
            for (int j = 0; j < 4; j++) kf[j] = Ks[(tx * 4 + j) * 65 + d];
            #pragma unroll
            for (int i = 0; i < 4; i++)
                #pragma unroll
                for (int j = 0; j < 4; j++)
                    sacc[i][j] = fmaf(qf[i], kf[j], sacc[i][j]);
        }

        const bool diag = (kt == nkt - 1);
        #pragma unroll
        for (int i = 0; i < 4; i++) {
            #pragma unroll
            for (int j = 0; j < 4; j++) {
                float sv = sacc[i][j] * 0.125f;
                sv += (1.0f - Ms[tx * 4 + j]) * (-1e4f);
                if (diag) {
                    int qg = q0 + ty * 4 + i;
                    int kg = k0 + tx * 4 + j;
                    if (kg > qg) sv += -1e10f;
                }
                sacc[i][j] = sv;
            }
        }

        #pragma unroll
        for (int i = 0; i < 4; i++) {
            float mm = fmaxf(fmaxf(sacc[i][0], sacc[i][1]), fmaxf(sacc[i][2], sacc[i][3]));
            #pragma unroll
            for (int off = 8; off >= 1; off >>= 1)
                mm = fmaxf(mm, __shfl_xor_sync(0xffffffffu, mm, off));
            float mnew  = fmaxf(m_run[i], mm);
            float alpha = __expf(m_run[i] - mnew);
            float ls = 0.0f;
            #pragma unroll
            for (int j = 0; j < 4; j++) {
                float p = __expf(sacc[i][j] - mnew);
                Ps[(ty * 4 + i) * 64 + tx * 4 + j] = p;
                ls += p;
            }
            #pragma unroll
            for (int off = 8; off >= 1; off >>= 1)
                ls += __shfl_xor_sync(0xffffffffu, ls, off);
            l_run[i] = l_run[i] * alpha + ls;
            m_run[i] = mnew;
            #pragma unroll
            for (int j = 0; j < 4; j++) Oacc[i][j] *= alpha;
        }
        __syncthreads();

        #pragma unroll 4
        for (int kk = 0; kk < 64; kk++) {
            float pf[4], vf[4];
            #pragma unroll
            for (int i = 0; i < 4; i++) pf[i] = Ps[(ty * 4 + i) * 64 + kk];
            #pragma unroll
            for (int j = 0; j < 4; j++) vf[j] = Vs[kk * 65 + tx * 4 + j];
            #pragma unroll
            for (int i = 0; i < 4; i++)
                #pragma unroll
                for (int j = 0; j < 4; j++)
                    Oacc[i][j] = fmaf(pf[i], vf[j], Oacc[i][j]);
        }
        __syncthreads();
    }

    float* Cb = Ctx + (size_t)(b * SS) * HH + h * HD;
    #pragma unroll
    for (int i = 0; i < 4; i++) {
        float inv_l = 1.0f / l_run[i];
        #pragma unroll
        for (int j = 0; j < 4; j++)
            Cb[(size_t)(q0 + ty * 4 + i) * HH + tx * 4 + j] = Oacc[i][j] * inv_l;
    }
}

// ---------------------------------------------------------------------------
// launcher
// ---------------------------------------------------------------------------
extern "C" void kernel_launch(void* const* d_in, const int* in_sizes, int n_in,
                              void* d_out, int out_size)
{
    const float* X    = (const float*)d_in[0];
    const float* mask = (const float*)d_in[1];
    const float* Wq   = (const float*)d_in[2];
    const float* bq   = (const float*)d_in[3];
    const float* Wk   = (const float*)d_in[4];
    const float* bk   = (const float*)d_in[5];
    const float* Wv   = (const float*)d_in[6];
    const float* bv   = (const float*)d_in[7];
    const float* Wo   = (const float*)d_in[8];
    const float* bo   = (const float*)d_in[9];
    float* out = (float*)d_out;

    float *qp, *kp, *vp, *cp;
    __nv_bfloat16 *xhi, *xlo, *chi, *clo, *whi, *wlo;
    cudaGetSymbolAddress((void**)&qp, g_Q);
    cudaGetSymbolAddress((void**)&kp, g_K);
    cudaGetSymbolAddress((void**)&vp, g_V);
    cudaGetSymbolAddress((void**)&cp, g_C);
    cudaGetSymbolAddress((void**)&xhi, g_Xhi);
    cudaGetSymbolAddress((void**)&xlo, g_Xlo);
    cudaGetSymbolAddress((void**)&chi, g_Chi);
    cudaGetSymbolAddress((void**)&clo, g_Clo);
    cudaGetSymbolAddress((void**)&whi, g_Whi);
    cudaGetSymbolAddress((void**)&wlo, g_Wlo);

    cudaFuncSetAttribute(tc_gemm, cudaFuncAttributeMaxDynamicSharedMemorySize, GT_SMEM);
    cudaFuncSetAttribute(attn_kernel, cudaFuncAttributeMaxDynamicSharedMemorySize, ATTN_SMEM);

    // prep: splits + transposed weights + rope table
    split_kernel<<<(MM * HH / 4 + 255) / 256, 256>>>(X, xhi, xlo, MM * HH / 4);
    wsplit_kernel<<<dim3(HH / 32, HH / 32, 4), dim3(32, 8)>>>(Wq, Wk, Wv, Wo);
    rope_table_kernel<<<(SS * 32 + 255) / 256, 256>>>();

    // projections (mma.sync bf16x3)
    dim3 gg(HH / 128, MM / 128);
    tc_gemm<<<gg, 256, GT_SMEM>>>(xhi, xlo, whi + 0 * (size_t)HH * HH, wlo + 0 * (size_t)HH * HH, bq, qp);
    tc_gemm<<<gg, 256, GT_SMEM>>>(xhi, xlo, whi + 1 * (size_t)HH * HH, wlo + 1 * (size_t)HH * HH, bk, kp);
    tc_gemm<<<gg, 256, GT_SMEM>>>(xhi, xlo, whi + 2 * (size_t)HH * HH, wlo + 2 * (size_t)HH * HH, bv, vp);

    rope_apply_kernel<<<(MM * NHEAD * 32 + 255) / 256, 256>>>(qp, kp);

    attn_kernel<<<dim3(SS / 64, NHEAD, BB), 256, ATTN_SMEM>>>(qp, kp, vp, mask, cp);

    // output projection
    split_kernel<<<(MM * HH / 4 + 255) / 256, 256>>>(cp, chi, clo, MM * HH / 4);
    tc_gemm<<<gg, 256, GT_SMEM>>>(chi, clo, whi + 3 * (size_t)HH * HH, wlo + 3 * (size_t)HH * HH, bo, out);
}